// round 2
// baseline (speedup 1.0000x reference)
#include <cuda_runtime.h>
#include <cstdint>

#define NROWS 1024
#define DF    12
#define NMASK 4096          // 2^D
#define KSEL  32
#define NCLS  10

// Scratch (no cudaMalloc allowed)
__device__ float g_cap_lookup[NMASK];   // cap_lookup[mask], [0]=0
__device__ float g_partial[8][16];      // per-block h3 partial sums

// ---------------------------------------------------------------------------
// Kernel 1: encoder MLP, per-block partial sums of h3 (deterministic)
// 8 blocks x 128 threads, 1 row per thread
// ---------------------------------------------------------------------------
__global__ void enc_kernel(const float* __restrict__ X,
                           const float* __restrict__ w1, const float* __restrict__ b1,
                           const float* __restrict__ w2, const float* __restrict__ b2,
                           const float* __restrict__ lng, const float* __restrict__ lnb,
                           const float* __restrict__ w3, const float* __restrict__ b3)
{
    __shared__ float sw1[32*12], sb1[32], sw2[16*32], sb2[16];
    __shared__ float slg[16], slb[16], sw3[16*16], sb3[16];
    __shared__ float wsum[4][16];

    int tid = threadIdx.x;
    for (int i = tid; i < 384; i += 128) sw1[i] = w1[i];
    for (int i = tid; i < 512; i += 128) sw2[i] = w2[i];
    for (int i = tid; i < 256; i += 128) sw3[i] = w3[i];
    if (tid < 32) sb1[tid] = b1[tid];
    if (tid < 16) { sb2[tid]=b2[tid]; slg[tid]=lng[tid]; slb[tid]=lnb[tid]; sb3[tid]=b3[tid]; }
    __syncthreads();

    int row = blockIdx.x * 128 + tid;
    float x[DF];
#pragma unroll
    for (int d = 0; d < DF; d++) x[d] = X[row*DF + d];

    // h1 = relu(X w1^T + b1) fused into h2 accumulation (h1 never stored)
    float h2[16];
#pragma unroll
    for (int o = 0; o < 16; o++) h2[o] = sb2[o];
#pragma unroll
    for (int o1 = 0; o1 < 32; o1++) {
        float a = sb1[o1];
#pragma unroll
        for (int d = 0; d < DF; d++) a = fmaf(x[d], sw1[o1*DF + d], a);
        a = fmaxf(a, 0.0f);
#pragma unroll
        for (int o2 = 0; o2 < 16; o2++) h2[o2] = fmaf(a, sw2[o2*32 + o1], h2[o2]);
    }
#pragma unroll
    for (int o = 0; o < 16; o++) h2[o] = fmaxf(h2[o], 0.0f);

    // LayerNorm over 16
    float mu = 0.0f;
#pragma unroll
    for (int o = 0; o < 16; o++) mu += h2[o];
    mu *= (1.0f/16.0f);
    float var = 0.0f;
#pragma unroll
    for (int o = 0; o < 16; o++) { float dd = h2[o] - mu; var = fmaf(dd, dd, var); }
    var *= (1.0f/16.0f);
    float rs = rsqrtf(var + 1e-5f);
    float hn[16];
#pragma unroll
    for (int o = 0; o < 16; o++) hn[o] = fmaf((h2[o]-mu)*rs, slg[o], slb[o]);

    // h3 = hn @ w3^T + b3
    float h3[16];
#pragma unroll
    for (int o = 0; o < 16; o++) {
        float a = sb3[o];
#pragma unroll
        for (int f = 0; f < 16; f++) a = fmaf(hn[f], sw3[o*16 + f], a);
        h3[o] = a;
    }

    // deterministic reduction: warp shuffle then fixed-order cross-warp
    int lane = tid & 31, wid = tid >> 5;
#pragma unroll
    for (int o = 0; o < 16; o++) {
        float v = h3[o];
#pragma unroll
        for (int off = 16; off; off >>= 1) v += __shfl_xor_sync(0xffffffffu, v, off);
        if (lane == 0) wsum[wid][o] = v;
    }
    __syncthreads();
    if (tid < 16) {
        float s = wsum[0][tid] + wsum[1][tid] + wsum[2][tid] + wsum[3][tid];
        g_partial[blockIdx.x][tid] = s;
    }
}

// ---------------------------------------------------------------------------
// Kernel 2: latent -> capacity increments -> SOS zeta transform -> cap_lookup
// 1 block x 1024 threads. Also writes the `caps` output (out[10240..14334]).
// ---------------------------------------------------------------------------
__global__ void caps_kernel(const float* __restrict__ cw1, const float* __restrict__ cb1,
                            const float* __restrict__ cw2, const float* __restrict__ cb2,
                            float* __restrict__ out)
{
    __shared__ float g[NMASK];
    __shared__ float latent[16], hc[16];
    int tid = threadIdx.x;

    if (tid < 16) {
        float s = 0.0f;
#pragma unroll
        for (int b = 0; b < 8; b++) s += g_partial[b][tid];
        latent[tid] = s * (1.0f/1024.0f);
    }
    __syncthreads();
    if (tid < 16) {
        float a = cb1[tid];
#pragma unroll
        for (int f = 0; f < 16; f++) a = fmaf(latent[f], cw1[tid*16 + f], a);
        hc[tid] = fmaxf(a, 0.0f);
    }
    __syncthreads();

    if (tid == 0) g[0] = 0.0f;
    for (int m = tid; m < NMASK-1; m += 1024) {
        const float4* wr = (const float4*)(cw2 + m*16);
        float4 a0 = wr[0], a1 = wr[1], a2 = wr[2], a3 = wr[3];
        float z = cb2[m];
        z = fmaf(a0.x, hc[0],  z); z = fmaf(a0.y, hc[1],  z);
        z = fmaf(a0.z, hc[2],  z); z = fmaf(a0.w, hc[3],  z);
        z = fmaf(a1.x, hc[4],  z); z = fmaf(a1.y, hc[5],  z);
        z = fmaf(a1.z, hc[6],  z); z = fmaf(a1.w, hc[7],  z);
        z = fmaf(a2.x, hc[8],  z); z = fmaf(a2.y, hc[9],  z);
        z = fmaf(a2.z, hc[10], z); z = fmaf(a2.w, hc[11], z);
        z = fmaf(a3.x, hc[12], z); z = fmaf(a3.y, hc[13], z);
        z = fmaf(a3.z, hc[14], z); z = fmaf(a3.w, hc[15], z);
        float inc = 0.1f / (1.0f + __expf(-z));   // sigmoid(z)*0.1
        g[m + 1] = inc;
    }
    __syncthreads();

    // subset-sum (zeta) transform: g[m] = sum_{b subset m} inc[b]
#pragma unroll
    for (int bit = 0; bit < DF; bit++) {
        for (int i = tid; i < NMASK/2; i += 1024) {
            int low = i & ((1 << bit) - 1);
            int m = ((i >> bit) << (bit + 1)) | (1 << bit) | low;
            g[m] += g[m ^ (1 << bit)];
        }
        __syncthreads();
    }

    float nrm = g[NMASK-1] + 1e-8f;
    for (int m = tid; m < NMASK; m += 1024) {
        float c = g[m] / nrm;
        g_cap_lookup[m] = c;
        if (m >= 1) out[NROWS*NCLS + m - 1] = c;   // caps output (S=4095)
    }
}

// ---------------------------------------------------------------------------
// Kernel 3: pairwise Choquet sims + top-32 softmax vote.
// 1024 blocks (one per query row i) x 1024 threads (one per candidate j).
// ---------------------------------------------------------------------------
__global__ void __launch_bounds__(1024, 1)
pairs_kernel(const float* __restrict__ X, const int* __restrict__ y,
             float* __restrict__ out)
{
    __shared__ float caps[NMASK];
    __shared__ float xi[DF];
    __shared__ float sv[NROWS];
    __shared__ int   si[NROWS];

    const int i   = blockIdx.x;
    const int tid = threadIdx.x;
    const int lane = tid & 31, w = tid >> 5;

    for (int m = tid; m < NMASK; m += 1024) caps[m] = g_cap_lookup[m];
    if (tid < DF) xi[tid] = X[i*DF + tid];
    __syncthreads();

    const int j = tid;
    float val;
    if (j == i) {
        val = -1e9f;   // exclude self
    } else {
        // keys: |diff| bits (monotone for >=0 floats), low 4 bits carry feature id
        unsigned k[DF];
#pragma unroll
        for (int d = 0; d < DF; d++) {
            float diff = fabsf(X[j*DF + d] - xi[d]);
            k[d] = (__float_as_uint(diff) & 0xFFFFFFF0u) | (unsigned)d;
        }
        // insertion-sort network, descending |diff| == ascending s=exp(-|diff|)
#pragma unroll
        for (int a = 1; a < DF; a++)
#pragma unroll
            for (int b = a; b > 0; b--) {
                unsigned lo = umin(k[b-1], k[b]);
                unsigned hi = umax(k[b-1], k[b]);
                k[b-1] = hi; k[b] = lo;
            }
        // Choquet integral: sum_k (v_k - v_{k-1}) * cap[suffix_mask_k]
        float prev = 0.0f, sim = 0.0f;
        unsigned mask = (unsigned)(NMASK - 1);
#pragma unroll
        for (int p = 0; p < DF; p++) {
            float dpos = __uint_as_float(k[p] & 0xFFFFFFF0u);
            float v = __expf(-dpos);
            sim = fmaf(v - prev, caps[mask], sim);
            prev = v;
            mask &= ~(1u << (k[p] & 0xFu));
        }
        val = sim;
    }

    // per-warp bitonic sort (descending) of (val, idx) across lanes
    int idx = j;
#pragma unroll
    for (int kk = 2; kk <= 32; kk <<= 1) {
#pragma unroll
        for (int jj = kk >> 1; jj > 0; jj >>= 1) {
            float ov = __shfl_xor_sync(0xffffffffu, val, jj);
            int   oi = __shfl_xor_sync(0xffffffffu, idx, jj);
            bool lower   = (lane & jj) == 0;
            bool dirdesc = (lane & kk) == 0;
            bool takeMax = dirdesc ? lower : !lower;
            bool sw = takeMax ? (ov > val) : (ov < val);
            if (sw) { val = ov; idx = oi; }
        }
    }
    sv[w*32 + lane] = val;
    si[w*32 + lane] = idx;
    __syncthreads();

    // warp 0: 32-way merge of sorted lists -> exact global top-32
    if (w == 0) {
        int pos = 0;
        float myV = 0.0f; int myI = 0;
#pragma unroll 1
        for (int t = 0; t < KSEL; ++t) {
            float hv = sv[lane*32 + pos];
            int   hi = si[lane*32 + pos];
            float bv = hv; int bl = lane;
#pragma unroll
            for (int off = 16; off; off >>= 1) {
                float o  = __shfl_xor_sync(0xffffffffu, bv, off);
                int   ol = __shfl_xor_sync(0xffffffffu, bl, off);
                if (o > bv || (o == bv && ol < bl)) { bv = o; bl = ol; }
            }
            int widx = __shfl_sync(0xffffffffu, hi, bl);
            if (lane == t) { myV = bv; myI = widx; }
            if (lane == bl) pos++;
        }
        // softmax over top-32 (lane t holds t-th largest; lane 0 = max)
        float vmax = __shfl_sync(0xffffffffu, myV, 0);
        float e = __expf((myV - vmax) * 2.0f);   // 1/TEMP = 2
        float s = e;
#pragma unroll
        for (int off = 16; off; off >>= 1) s += __shfl_xor_sync(0xffffffffu, s, off);
        float wgt = e / s;
        int label = y[myI];
        // deterministic per-class vote reduction
#pragma unroll
        for (int c = 0; c < NCLS; c++) {
            float vc = (label == c) ? wgt : 0.0f;
#pragma unroll
            for (int off = 16; off; off >>= 1) vc += __shfl_xor_sync(0xffffffffu, vc, off);
            if (lane == 0) out[i*NCLS + c] = vc;
        }
    }
}

// ---------------------------------------------------------------------------
extern "C" void kernel_launch(void* const* d_in, const int* in_sizes, int n_in,
                              void* d_out, int out_size)
{
    const float* X    = (const float*)d_in[0];
    const int*   y    = (const int*)  d_in[1];
    const float* w1   = (const float*)d_in[2];
    const float* b1   = (const float*)d_in[3];
    const float* w2   = (const float*)d_in[4];
    const float* b2   = (const float*)d_in[5];
    const float* lng  = (const float*)d_in[6];
    const float* lnb  = (const float*)d_in[7];
    const float* w3   = (const float*)d_in[8];
    const float* b3   = (const float*)d_in[9];
    const float* cw1  = (const float*)d_in[10];
    const float* cb1  = (const float*)d_in[11];
    const float* cw2  = (const float*)d_in[12];
    const float* cb2  = (const float*)d_in[13];
    float* out = (float*)d_out;

    enc_kernel<<<8, 128>>>(X, w1, b1, w2, b2, lng, lnb, w3, b3);
    caps_kernel<<<1, 1024>>>(cw1, cb1, cw2, cb2, out);
    pairs_kernel<<<1024, 1024>>>(X, y, out);
}

// round 3
// speedup vs baseline: 1.3103x; 1.3103x over previous
#include <cuda_runtime.h>
#include <cstdint>

#define NROWS 1024
#define DF    12
#define NMASK 4096          // 2^D
#define KSEL  32
#define NCLS  10

// Scratch (no cudaMalloc allowed)
__device__ float g_cap_lookup[NMASK];    // cap_lookup[mask], [0]=0
__device__ float g_incr[NMASK];          // increments by mask, [0]=0
__device__ float g_partial[32][16];      // per-block h3 partial sums

// ---------------------------------------------------------------------------
// Kernel 1: encoder MLP. 32 blocks x 32 threads, 1 row/thread.
// Weights read straight from global via LDG.128 (uniform addr -> L1 broadcast).
// ---------------------------------------------------------------------------
__global__ void __launch_bounds__(32, 1)
enc_kernel(const float* __restrict__ X,
           const float* __restrict__ w1, const float* __restrict__ b1,
           const float* __restrict__ w2, const float* __restrict__ b2,
           const float* __restrict__ lng, const float* __restrict__ lnb,
           const float* __restrict__ w3, const float* __restrict__ b3)
{
    const int lane = threadIdx.x;
    const int row  = blockIdx.x * 32 + lane;

    // X row: 12 floats = 3 x float4 (48B rows, 16B aligned)
    const float4* xr = (const float4*)(X + row * DF);
    float4 x0 = xr[0], x1 = xr[1], x2 = xr[2];

    // h1 = relu(X @ w1^T + b1)  -- w1 rows are 12 floats = 3 float4
    float h1[32];
#pragma unroll
    for (int o = 0; o < 32; o++) {
        const float4* wr = (const float4*)(w1 + o * DF);
        float4 a0 = wr[0], a1 = wr[1], a2 = wr[2];
        float a = b1[o];
        a = fmaf(x0.x, a0.x, a); a = fmaf(x0.y, a0.y, a);
        a = fmaf(x0.z, a0.z, a); a = fmaf(x0.w, a0.w, a);
        a = fmaf(x1.x, a1.x, a); a = fmaf(x1.y, a1.y, a);
        a = fmaf(x1.z, a1.z, a); a = fmaf(x1.w, a1.w, a);
        a = fmaf(x2.x, a2.x, a); a = fmaf(x2.y, a2.y, a);
        a = fmaf(x2.z, a2.z, a); a = fmaf(x2.w, a2.w, a);
        h1[o] = fmaxf(a, 0.0f);
    }

    // h2 = relu(h1 @ w2^T + b2)  -- w2 rows are 32 floats = 8 float4
    float h2[16];
#pragma unroll
    for (int o = 0; o < 16; o++) {
        const float4* wr = (const float4*)(w2 + o * 32);
        float a = b2[o];
#pragma unroll
        for (int q = 0; q < 8; q++) {
            float4 v = wr[q];
            a = fmaf(h1[q*4+0], v.x, a);
            a = fmaf(h1[q*4+1], v.y, a);
            a = fmaf(h1[q*4+2], v.z, a);
            a = fmaf(h1[q*4+3], v.w, a);
        }
        h2[o] = fmaxf(a, 0.0f);
    }

    // LayerNorm over 16
    float mu = 0.0f;
#pragma unroll
    for (int o = 0; o < 16; o++) mu += h2[o];
    mu *= (1.0f/16.0f);
    float var = 0.0f;
#pragma unroll
    for (int o = 0; o < 16; o++) { float dd = h2[o] - mu; var = fmaf(dd, dd, var); }
    var *= (1.0f/16.0f);
    float rs = rsqrtf(var + 1e-5f);
    float hn[16];
#pragma unroll
    for (int o = 0; o < 16; o++) hn[o] = fmaf((h2[o]-mu)*rs, lng[o], lnb[o]);

    // h3 = hn @ w3^T + b3  -- w3 rows are 16 floats = 4 float4
    // then deterministic warp reduction, write partial
#pragma unroll
    for (int o = 0; o < 16; o++) {
        const float4* wr = (const float4*)(w3 + o * 16);
        float a = b3[o];
#pragma unroll
        for (int q = 0; q < 4; q++) {
            float4 v = wr[q];
            a = fmaf(hn[q*4+0], v.x, a);
            a = fmaf(hn[q*4+1], v.y, a);
            a = fmaf(hn[q*4+2], v.z, a);
            a = fmaf(hn[q*4+3], v.w, a);
        }
#pragma unroll
        for (int off = 16; off; off >>= 1) a += __shfl_xor_sync(0xffffffffu, a, off);
        if (lane == 0) g_partial[blockIdx.x][o] = a;
    }
}

// ---------------------------------------------------------------------------
// Kernel 2: capacity increments, 32 blocks x 128 threads (1 mask/thread).
// ---------------------------------------------------------------------------
__global__ void incr_kernel(const float* __restrict__ cw1, const float* __restrict__ cb1,
                            const float* __restrict__ cw2, const float* __restrict__ cb2)
{
    __shared__ float lat[16], hc[16];
    int tid = threadIdx.x;

    if (tid < 16) {
        float s = 0.0f;
#pragma unroll
        for (int b = 0; b < 32; b++) s += g_partial[b][tid];
        lat[tid] = s * (1.0f/1024.0f);
    }
    __syncthreads();
    if (tid < 16) {
        float a = cb1[tid];
#pragma unroll
        for (int f = 0; f < 16; f++) a = fmaf(lat[f], cw1[tid*16 + f], a);
        hc[tid] = fmaxf(a, 0.0f);
    }
    __syncthreads();

    int m = blockIdx.x * 128 + tid;          // mask in [0, 4096)
    if (m == 0) { g_incr[0] = 0.0f; return; }
    int r = m - 1;                           // cw2 row
    const float4* wr = (const float4*)(cw2 + r*16);
    float4 a0 = wr[0], a1 = wr[1], a2 = wr[2], a3 = wr[3];
    float z = cb2[r];
    z = fmaf(a0.x, hc[0],  z); z = fmaf(a0.y, hc[1],  z);
    z = fmaf(a0.z, hc[2],  z); z = fmaf(a0.w, hc[3],  z);
    z = fmaf(a1.x, hc[4],  z); z = fmaf(a1.y, hc[5],  z);
    z = fmaf(a1.z, hc[6],  z); z = fmaf(a1.w, hc[7],  z);
    z = fmaf(a2.x, hc[8],  z); z = fmaf(a2.y, hc[9],  z);
    z = fmaf(a2.z, hc[10], z); z = fmaf(a2.w, hc[11], z);
    z = fmaf(a3.x, hc[12], z); z = fmaf(a3.y, hc[13], z);
    z = fmaf(a3.z, hc[14], z); z = fmaf(a3.w, hc[15], z);
    g_incr[m] = 0.1f / (1.0f + __expf(-z));
}

// ---------------------------------------------------------------------------
// Kernel 3: zeta (subset-sum) transform, normalize, write cap_lookup + caps out
// ---------------------------------------------------------------------------
__global__ void zeta_kernel(float* __restrict__ out)
{
    __shared__ float g[NMASK];
    int tid = threadIdx.x;
    for (int m = tid; m < NMASK; m += 1024) g[m] = g_incr[m];
    __syncthreads();

#pragma unroll
    for (int bit = 0; bit < DF; bit++) {
        for (int i = tid; i < NMASK/2; i += 1024) {
            int low = i & ((1 << bit) - 1);
            int m = ((i >> bit) << (bit + 1)) | (1 << bit) | low;
            g[m] += g[m ^ (1 << bit)];
        }
        __syncthreads();
    }

    float nrm = g[NMASK-1] + 1e-8f;
    for (int m = tid; m < NMASK; m += 1024) {
        float c = g[m] / nrm;
        g_cap_lookup[m] = c;
        if (m >= 1) out[NROWS*NCLS + m - 1] = c;   // caps output (S=4095)
    }
}

// ---------------------------------------------------------------------------
// Kernel 4: pairwise Choquet sims + parallel top-32 merge + softmax vote.
// 1024 blocks (one per query row) x 1024 threads (one per candidate).
// ---------------------------------------------------------------------------
__global__ void __launch_bounds__(1024, 1)
pairs_kernel(const float* __restrict__ X, const int* __restrict__ y,
             float* __restrict__ out)
{
    __shared__ float caps[NMASK];
    __shared__ float sA[NROWS];  __shared__ int iA[NROWS];
    __shared__ float sB[512];    __shared__ int iB[512];

    const int i   = blockIdx.x;
    const int tid = threadIdx.x;
    const int lane = tid & 31, w = tid >> 5;

    for (int m = tid; m < NMASK; m += 1024) caps[m] = g_cap_lookup[m];

    // query row features (uniform address -> L1 broadcast)
    const float4* xir = (const float4*)(X + i * DF);
    float4 q0 = xir[0], q1 = xir[1], q2 = xir[2];
    __syncthreads();

    const int j = tid;
    float val;
    if (j == i) {
        val = -1e9f;   // exclude self
    } else {
        const float4* xjr = (const float4*)(X + j * DF);
        float4 p0 = xjr[0], p1 = xjr[1], p2 = xjr[2];
        // keys: |diff| float bits (monotone for >=0), low 4 bits = feature id
        unsigned k[DF];
        k[0]  = (__float_as_uint(fabsf(p0.x - q0.x)) & 0xFFFFFFF0u) | 0u;
        k[1]  = (__float_as_uint(fabsf(p0.y - q0.y)) & 0xFFFFFFF0u) | 1u;
        k[2]  = (__float_as_uint(fabsf(p0.z - q0.z)) & 0xFFFFFFF0u) | 2u;
        k[3]  = (__float_as_uint(fabsf(p0.w - q0.w)) & 0xFFFFFFF0u) | 3u;
        k[4]  = (__float_as_uint(fabsf(p1.x - q1.x)) & 0xFFFFFFF0u) | 4u;
        k[5]  = (__float_as_uint(fabsf(p1.y - q1.y)) & 0xFFFFFFF0u) | 5u;
        k[6]  = (__float_as_uint(fabsf(p1.z - q1.z)) & 0xFFFFFFF0u) | 6u;
        k[7]  = (__float_as_uint(fabsf(p1.w - q1.w)) & 0xFFFFFFF0u) | 7u;
        k[8]  = (__float_as_uint(fabsf(p2.x - q2.x)) & 0xFFFFFFF0u) | 8u;
        k[9]  = (__float_as_uint(fabsf(p2.y - q2.y)) & 0xFFFFFFF0u) | 9u;
        k[10] = (__float_as_uint(fabsf(p2.z - q2.z)) & 0xFFFFFFF0u) | 10u;
        k[11] = (__float_as_uint(fabsf(p2.w - q2.w)) & 0xFFFFFFF0u) | 11u;
        // insertion-sort network, descending |diff| == ascending s=exp(-|diff|)
#pragma unroll
        for (int a = 1; a < DF; a++)
#pragma unroll
            for (int b = a; b > 0; b--) {
                unsigned lo = umin(k[b-1], k[b]);
                unsigned hi = umax(k[b-1], k[b]);
                k[b-1] = hi; k[b] = lo;
            }
        // Choquet integral: sum_p (v_p - v_{p-1}) * cap[suffix_mask_p]
        float prev = 0.0f, sim = 0.0f;
        unsigned mask = (unsigned)(NMASK - 1);
#pragma unroll
        for (int p = 0; p < DF; p++) {
            float dpos = __uint_as_float(k[p] & 0xFFFFFFF0u);
            float v = __expf(-dpos);
            sim = fmaf(v - prev, caps[mask], sim);
            prev = v;
            mask &= ~(1u << (k[p] & 0xFu));
        }
        val = sim;
    }

    // per-warp bitonic sort (descending) of (val, idx) across lanes
    int idx = j;
#pragma unroll
    for (int kk = 2; kk <= 32; kk <<= 1) {
#pragma unroll
        for (int jj = kk >> 1; jj > 0; jj >>= 1) {
            float ov = __shfl_xor_sync(0xffffffffu, val, jj);
            int   oi = __shfl_xor_sync(0xffffffffu, idx, jj);
            bool lower   = (lane & jj) == 0;
            bool dirdesc = (lane & kk) == 0;
            bool takeMax = dirdesc ? lower : !lower;
            bool sw = takeMax ? (ov > val) : (ov < val);
            if (sw) { val = ov; idx = oi; }
        }
    }
    sA[w*32 + lane] = val;
    iA[w*32 + lane] = idx;
    __syncthreads();

    // parallel merge tree: 32 sorted lists -> 1, keeping top-32 at each merge.
    // merge(A desc, B desc): C[k] = max(A[k], B[31-k]) is bitonic and holds
    // the 32 largest; 5-stage bitonic clean sorts it descending.
#define MERGE_STAGE(NACT, SRCV, SRCI, DSTV, DSTI)                             \
    if (w < (NACT)) {                                                         \
        float av = SRCV[(2*w)*32 + lane];                                     \
        int   ai = SRCI[(2*w)*32 + lane];                                     \
        float bv = SRCV[(2*w+1)*32 + (31 - lane)];                            \
        int   bi = SRCI[(2*w+1)*32 + (31 - lane)];                            \
        float mv; int mi;                                                     \
        if (av >= bv) { mv = av; mi = ai; } else { mv = bv; mi = bi; }        \
        _Pragma("unroll")                                                     \
        for (int off = 16; off; off >>= 1) {                                  \
            float ov2 = __shfl_xor_sync(0xffffffffu, mv, off);                \
            int   oi2 = __shfl_xor_sync(0xffffffffu, mi, off);                \
            bool up = (lane & off) == 0;                                      \
            bool take = up ? (ov2 > mv) : (ov2 < mv);                         \
            if (take) { mv = ov2; mi = oi2; }                                 \
        }                                                                     \
        DSTV[w*32 + lane] = mv; DSTI[w*32 + lane] = mi;                       \
    }                                                                         \
    __syncthreads();

    MERGE_STAGE(16, sA, iA, sB, iB)   // 32 -> 16
    MERGE_STAGE(8,  sB, iB, sA, iA)   // 16 -> 8
    MERGE_STAGE(4,  sA, iA, sB, iB)   // 8  -> 4
    MERGE_STAGE(2,  sB, iB, sA, iA)   // 4  -> 2
#undef MERGE_STAGE

    // final merge (2 -> 1) + softmax vote in warp 0, all in registers
    if (w == 0) {
        float av = sA[lane];
        int   ai = iA[lane];
        float bv = sA[32 + (31 - lane)];
        int   bi = iA[32 + (31 - lane)];
        float mv; int mi;
        if (av >= bv) { mv = av; mi = ai; } else { mv = bv; mi = bi; }
#pragma unroll
        for (int off = 16; off; off >>= 1) {
            float ov2 = __shfl_xor_sync(0xffffffffu, mv, off);
            int   oi2 = __shfl_xor_sync(0xffffffffu, mi, off);
            bool up = (lane & off) == 0;
            bool take = up ? (ov2 > mv) : (ov2 < mv);
            if (take) { mv = ov2; mi = oi2; }
        }
        // lane t holds t-th largest (descending); lane 0 = max
        float vmax = __shfl_sync(0xffffffffu, mv, 0);
        float e = __expf((mv - vmax) * 2.0f);   // 1/TEMP = 2
        float s = e;
#pragma unroll
        for (int off = 16; off; off >>= 1) s += __shfl_xor_sync(0xffffffffu, s, off);
        float wgt = e / s;
        int label = y[mi];
#pragma unroll
        for (int c = 0; c < NCLS; c++) {
            float vc = (label == c) ? wgt : 0.0f;
#pragma unroll
            for (int off = 16; off; off >>= 1) vc += __shfl_xor_sync(0xffffffffu, vc, off);
            if (lane == 0) out[i*NCLS + c] = vc;
        }
    }
}

// ---------------------------------------------------------------------------
extern "C" void kernel_launch(void* const* d_in, const int* in_sizes, int n_in,
                              void* d_out, int out_size)
{
    const float* X    = (const float*)d_in[0];
    const int*   y    = (const int*)  d_in[1];
    const float* w1   = (const float*)d_in[2];
    const float* b1   = (const float*)d_in[3];
    const float* w2   = (const float*)d_in[4];
    const float* b2   = (const float*)d_in[5];
    const float* lng  = (const float*)d_in[6];
    const float* lnb  = (const float*)d_in[7];
    const float* w3   = (const float*)d_in[8];
    const float* b3   = (const float*)d_in[9];
    const float* cw1  = (const float*)d_in[10];
    const float* cb1  = (const float*)d_in[11];
    const float* cw2  = (const float*)d_in[12];
    const float* cb2  = (const float*)d_in[13];
    float* out = (float*)d_out;

    enc_kernel<<<32, 32>>>(X, w1, b1, w2, b2, lng, lnb, w3, b3);
    incr_kernel<<<32, 128>>>(cw1, cb1, cw2, cb2);
    zeta_kernel<<<1, 1024>>>(out);
    pairs_kernel<<<1024, 1024>>>(X, y, out);
}

// round 4
// speedup vs baseline: 1.7174x; 1.3107x over previous
#include <cuda_runtime.h>
#include <cstdint>

#define NROWS 1024
#define DF    12
#define NMASK 4096          // 2^D
#define KSEL  32
#define NCLS  10

// Scratch (no cudaMalloc allowed)
__device__ float g_cap_lookup[NMASK];     // cap_lookup[mask], [0]=0
__device__ float g_incr[NMASK];           // increments by mask, [0]=0
__device__ float g_partial[32][16];       // per-block h3 partial sums
__device__ float g_sims[NROWS * NROWS];   // full similarity matrix (4MB)

// ---------------------------------------------------------------------------
// Kernel 1: encoder MLP. 32 blocks x 32 threads, 1 row/thread.
// ---------------------------------------------------------------------------
__global__ void __launch_bounds__(32, 1)
enc_kernel(const float* __restrict__ X,
           const float* __restrict__ w1, const float* __restrict__ b1,
           const float* __restrict__ w2, const float* __restrict__ b2,
           const float* __restrict__ lng, const float* __restrict__ lnb,
           const float* __restrict__ w3, const float* __restrict__ b3)
{
    const int lane = threadIdx.x;
    const int row  = blockIdx.x * 32 + lane;

    const float4* xr = (const float4*)(X + row * DF);
    float4 x0 = xr[0], x1 = xr[1], x2 = xr[2];

    float h1[32];
#pragma unroll
    for (int o = 0; o < 32; o++) {
        const float4* wr = (const float4*)(w1 + o * DF);
        float4 a0 = wr[0], a1 = wr[1], a2 = wr[2];
        float a = b1[o];
        a = fmaf(x0.x, a0.x, a); a = fmaf(x0.y, a0.y, a);
        a = fmaf(x0.z, a0.z, a); a = fmaf(x0.w, a0.w, a);
        a = fmaf(x1.x, a1.x, a); a = fmaf(x1.y, a1.y, a);
        a = fmaf(x1.z, a1.z, a); a = fmaf(x1.w, a1.w, a);
        a = fmaf(x2.x, a2.x, a); a = fmaf(x2.y, a2.y, a);
        a = fmaf(x2.z, a2.z, a); a = fmaf(x2.w, a2.w, a);
        h1[o] = fmaxf(a, 0.0f);
    }

    float h2[16];
#pragma unroll
    for (int o = 0; o < 16; o++) {
        const float4* wr = (const float4*)(w2 + o * 32);
        float a = b2[o];
#pragma unroll
        for (int q = 0; q < 8; q++) {
            float4 v = wr[q];
            a = fmaf(h1[q*4+0], v.x, a);
            a = fmaf(h1[q*4+1], v.y, a);
            a = fmaf(h1[q*4+2], v.z, a);
            a = fmaf(h1[q*4+3], v.w, a);
        }
        h2[o] = fmaxf(a, 0.0f);
    }

    float mu = 0.0f;
#pragma unroll
    for (int o = 0; o < 16; o++) mu += h2[o];
    mu *= (1.0f/16.0f);
    float var = 0.0f;
#pragma unroll
    for (int o = 0; o < 16; o++) { float dd = h2[o] - mu; var = fmaf(dd, dd, var); }
    var *= (1.0f/16.0f);
    float rs = rsqrtf(var + 1e-5f);
    float hn[16];
#pragma unroll
    for (int o = 0; o < 16; o++) hn[o] = fmaf((h2[o]-mu)*rs, lng[o], lnb[o]);

#pragma unroll
    for (int o = 0; o < 16; o++) {
        const float4* wr = (const float4*)(w3 + o * 16);
        float a = b3[o];
#pragma unroll
        for (int q = 0; q < 4; q++) {
            float4 v = wr[q];
            a = fmaf(hn[q*4+0], v.x, a);
            a = fmaf(hn[q*4+1], v.y, a);
            a = fmaf(hn[q*4+2], v.z, a);
            a = fmaf(hn[q*4+3], v.w, a);
        }
#pragma unroll
        for (int off = 16; off; off >>= 1) a += __shfl_xor_sync(0xffffffffu, a, off);
        if (lane == 0) g_partial[blockIdx.x][o] = a;
    }
}

// ---------------------------------------------------------------------------
// Kernel 2: capacity increments, 32 blocks x 128 threads (1 mask/thread).
// ---------------------------------------------------------------------------
__global__ void incr_kernel(const float* __restrict__ cw1, const float* __restrict__ cb1,
                            const float* __restrict__ cw2, const float* __restrict__ cb2)
{
    __shared__ float lat[16], hc[16];
    int tid = threadIdx.x;

    if (tid < 16) {
        float s = 0.0f;
#pragma unroll
        for (int b = 0; b < 32; b++) s += g_partial[b][tid];
        lat[tid] = s * (1.0f/1024.0f);
    }
    __syncthreads();
    if (tid < 16) {
        float a = cb1[tid];
#pragma unroll
        for (int f = 0; f < 16; f++) a = fmaf(lat[f], cw1[tid*16 + f], a);
        hc[tid] = fmaxf(a, 0.0f);
    }
    __syncthreads();

    int m = blockIdx.x * 128 + tid;
    if (m == 0) { g_incr[0] = 0.0f; return; }
    int r = m - 1;
    const float4* wr = (const float4*)(cw2 + r*16);
    float4 a0 = wr[0], a1 = wr[1], a2 = wr[2], a3 = wr[3];
    float z = cb2[r];
    z = fmaf(a0.x, hc[0],  z); z = fmaf(a0.y, hc[1],  z);
    z = fmaf(a0.z, hc[2],  z); z = fmaf(a0.w, hc[3],  z);
    z = fmaf(a1.x, hc[4],  z); z = fmaf(a1.y, hc[5],  z);
    z = fmaf(a1.z, hc[6],  z); z = fmaf(a1.w, hc[7],  z);
    z = fmaf(a2.x, hc[8],  z); z = fmaf(a2.y, hc[9],  z);
    z = fmaf(a2.z, hc[10], z); z = fmaf(a2.w, hc[11], z);
    z = fmaf(a3.x, hc[12], z); z = fmaf(a3.y, hc[13], z);
    z = fmaf(a3.z, hc[14], z); z = fmaf(a3.w, hc[15], z);
    g_incr[m] = 0.1f / (1.0f + __expf(-z));
}

// ---------------------------------------------------------------------------
// Kernel 3: zeta (subset-sum) transform, normalize, write cap_lookup + caps out
// ---------------------------------------------------------------------------
__global__ void zeta_kernel(float* __restrict__ out)
{
    __shared__ float g[NMASK];
    int tid = threadIdx.x;
    for (int m = tid; m < NMASK; m += 1024) g[m] = g_incr[m];
    __syncthreads();

#pragma unroll
    for (int bit = 0; bit < DF; bit++) {
        for (int i = tid; i < NMASK/2; i += 1024) {
            int low = i & ((1 << bit) - 1);
            int m = ((i >> bit) << (bit + 1)) | (1 << bit) | low;
            g[m] += g[m ^ (1 << bit)];
        }
        __syncthreads();
    }

    float nrm = g[NMASK-1] + 1e-8f;
    for (int m = tid; m < NMASK; m += 1024) {
        float c = g[m] / nrm;
        g_cap_lookup[m] = c;
        if (m >= 1) out[NROWS*NCLS + m - 1] = c;   // caps output (S=4095)
    }
}

// ---------------------------------------------------------------------------
// Kernel 4: symmetric Choquet tiles. 528 blocks (upper-tri 32x32 tiles) x 256.
// Each thread computes 4 pairs; tile staged in padded smem, both the tile and
// its transpose written coalesced to g_sims.
// ---------------------------------------------------------------------------
__global__ void __launch_bounds__(256, 6)
sym_kernel(const float* __restrict__ X)
{
    __shared__ float caps[NMASK];
    __shared__ float xi[32 * DF];
    __shared__ float tile[32][33];

    const int tid  = threadIdx.x;
    const int lane = tid & 31, w = tid >> 5;

    // triangular decode: blockIdx -> (I >= J)
    int b = blockIdx.x;
    int I = (int)((sqrtf(8.0f * (float)b + 1.0f) - 1.0f) * 0.5f);
    if (I * (I + 1) / 2 > b) I--;
    if ((I + 1) * (I + 2) / 2 <= b) I++;
    int J = b - I * (I + 1) / 2;

    // caps -> smem (4096 floats, 4 float4 per thread)
    {
        const float4* src = (const float4*)g_cap_lookup;
        float4* dst = (float4*)caps;
#pragma unroll
        for (int r = 0; r < 4; r++) dst[tid + 256*r] = src[tid + 256*r];
    }
    // I-tile rows -> smem (32 rows x 12 floats = 96 float4)
    if (tid < 96) ((float4*)xi)[tid] = ((const float4*)(X + I * 32 * DF))[tid];

    // J-tile row for this lane, kept in registers across all 4 sub-rows
    const int j = J * 32 + lane;
    const float4* xjr = (const float4*)(X + j * DF);
    float4 p0 = xjr[0], p1 = xjr[1], p2 = xjr[2];
    float pj[DF] = { p0.x, p0.y, p0.z, p0.w, p1.x, p1.y, p1.z, p1.w,
                     p2.x, p2.y, p2.z, p2.w };
    __syncthreads();

#pragma unroll
    for (int q = 0; q < 4; q++) {
        const int il = w + 8 * q;
        const int i  = I * 32 + il;
        float sim;
        if (i == j) {
            sim = -1e9f;                     // exclude self
        } else {
            const float* qr = &xi[il * DF];
            // keys: |diff| float bits (monotone, sign+low bits cleared), id in low 4
            unsigned k[DF];
#pragma unroll
            for (int d = 0; d < DF; d++) {
                float diff = pj[d] - qr[d];
                k[d] = (__float_as_uint(diff) & 0x7FFFFFF0u) | (unsigned)d;
            }
            // Batcher odd-even mergesort (descending), ~41 comparators for n=12
#pragma unroll
            for (int p = 1; p < DF; p <<= 1) {
#pragma unroll
                for (int kk = p; kk >= 1; kk >>= 1) {
#pragma unroll
                    for (int jj = kk % p; jj <= DF - 1 - kk; jj += 2 * kk) {
#pragma unroll
                        for (int ii = 0; ii < kk; ii++) {
                            int a = ii + jj, c = ii + jj + kk;
                            if (c < DF && (a / (2 * p)) == (c / (2 * p))) {
                                unsigned lo = umin(k[a], k[c]);
                                unsigned hi = umax(k[a], k[c]);
                                k[a] = hi; k[c] = lo;
                            }
                        }
                    }
                }
            }
            // Choquet: sum_p (v_p - v_{p-1}) * cap[suffix_mask_p]
            float prev = 0.0f; sim = 0.0f;
            unsigned mask = (unsigned)(NMASK - 1);
#pragma unroll
            for (int p = 0; p < DF; p++) {
                float dpos = __uint_as_float(k[p] & 0xFFFFFFF0u);
                float v = __expf(-dpos);
                sim = fmaf(v - prev, caps[mask], sim);
                prev = v;
                mask &= ~(1u << (k[p] & 0xFu));
            }
        }
        tile[il][lane] = sim;
    }
    __syncthreads();

    // coalesced writes: tile and (if off-diagonal) transpose
#pragma unroll
    for (int q = 0; q < 4; q++) {
        const int il = w + 8 * q;
        g_sims[(I * 32 + il) * NROWS + J * 32 + lane] = tile[il][lane];
    }
    if (I != J) {
#pragma unroll
        for (int q = 0; q < 4; q++) {
            const int il = w + 8 * q;
            g_sims[(J * 32 + il) * NROWS + I * 32 + lane] = tile[lane][il];
        }
    }
}

// ---------------------------------------------------------------------------
// Kernel 5: per-row top-32 + softmax vote. 1024 blocks x 1024 threads, 2/SM.
// ---------------------------------------------------------------------------
__global__ void __launch_bounds__(1024, 2)
topk_kernel(const int* __restrict__ y, float* __restrict__ out)
{
    __shared__ float sA[NROWS];  __shared__ int iA[NROWS];
    __shared__ float sB[512];    __shared__ int iB[512];

    const int i    = blockIdx.x;
    const int tid  = threadIdx.x;
    const int lane = tid & 31, w = tid >> 5;

    float val = g_sims[i * NROWS + tid];
    int   idx = tid;

    // per-warp bitonic sort (descending)
#pragma unroll
    for (int kk = 2; kk <= 32; kk <<= 1) {
#pragma unroll
        for (int jj = kk >> 1; jj > 0; jj >>= 1) {
            float ov = __shfl_xor_sync(0xffffffffu, val, jj);
            int   oi = __shfl_xor_sync(0xffffffffu, idx, jj);
            bool lower   = (lane & jj) == 0;
            bool dirdesc = (lane & kk) == 0;
            bool takeMax = dirdesc ? lower : !lower;
            bool sw = takeMax ? (ov > val) : (ov < val);
            if (sw) { val = ov; idx = oi; }
        }
    }
    sA[w*32 + lane] = val;
    iA[w*32 + lane] = idx;
    __syncthreads();

    // merge tree: 32 sorted lists -> 1 (top-32 kept per merge)
#define MERGE_STAGE(NACT, SRCV, SRCI, DSTV, DSTI)                             \
    if (w < (NACT)) {                                                         \
        float av = SRCV[(2*w)*32 + lane];                                     \
        int   ai = SRCI[(2*w)*32 + lane];                                     \
        float bv = SRCV[(2*w+1)*32 + (31 - lane)];                            \
        int   bi = SRCI[(2*w+1)*32 + (31 - lane)];                            \
        float mv; int mi;                                                     \
        if (av >= bv) { mv = av; mi = ai; } else { mv = bv; mi = bi; }        \
        _Pragma("unroll")                                                     \
        for (int off = 16; off; off >>= 1) {                                  \
            float ov2 = __shfl_xor_sync(0xffffffffu, mv, off);                \
            int   oi2 = __shfl_xor_sync(0xffffffffu, mi, off);                \
            bool up = (lane & off) == 0;                                      \
            bool take = up ? (ov2 > mv) : (ov2 < mv);                         \
            if (take) { mv = ov2; mi = oi2; }                                 \
        }                                                                     \
        DSTV[w*32 + lane] = mv; DSTI[w*32 + lane] = mi;                       \
    }                                                                         \
    __syncthreads();

    MERGE_STAGE(16, sA, iA, sB, iB)
    MERGE_STAGE(8,  sB, iB, sA, iA)
    MERGE_STAGE(4,  sA, iA, sB, iB)
    MERGE_STAGE(2,  sB, iB, sA, iA)
#undef MERGE_STAGE

    if (w == 0) {
        float av = sA[lane];
        int   ai = iA[lane];
        float bv = sA[32 + (31 - lane)];
        int   bi = iA[32 + (31 - lane)];
        float mv; int mi;
        if (av >= bv) { mv = av; mi = ai; } else { mv = bv; mi = bi; }
#pragma unroll
        for (int off = 16; off; off >>= 1) {
            float ov2 = __shfl_xor_sync(0xffffffffu, mv, off);
            int   oi2 = __shfl_xor_sync(0xffffffffu, mi, off);
            bool up = (lane & off) == 0;
            bool take = up ? (ov2 > mv) : (ov2 < mv);
            if (take) { mv = ov2; mi = oi2; }
        }
        float vmax = __shfl_sync(0xffffffffu, mv, 0);
        float e = __expf((mv - vmax) * 2.0f);   // 1/TEMP = 2
        float s = e;
#pragma unroll
        for (int off = 16; off; off >>= 1) s += __shfl_xor_sync(0xffffffffu, s, off);
        float wgt = e / s;
        int label = y[mi];
#pragma unroll
        for (int c = 0; c < NCLS; c++) {
            float vc = (label == c) ? wgt : 0.0f;
#pragma unroll
            for (int off = 16; off; off >>= 1) vc += __shfl_xor_sync(0xffffffffu, vc, off);
            if (lane == 0) out[i*NCLS + c] = vc;
        }
    }
}

// ---------------------------------------------------------------------------
extern "C" void kernel_launch(void* const* d_in, const int* in_sizes, int n_in,
                              void* d_out, int out_size)
{
    const float* X    = (const float*)d_in[0];
    const int*   y    = (const int*)  d_in[1];
    const float* w1   = (const float*)d_in[2];
    const float* b1   = (const float*)d_in[3];
    const float* w2   = (const float*)d_in[4];
    const float* b2   = (const float*)d_in[5];
    const float* lng  = (const float*)d_in[6];
    const float* lnb  = (const float*)d_in[7];
    const float* w3   = (const float*)d_in[8];
    const float* b3   = (const float*)d_in[9];
    const float* cw1  = (const float*)d_in[10];
    const float* cb1  = (const float*)d_in[11];
    const float* cw2  = (const float*)d_in[12];
    const float* cb2  = (const float*)d_in[13];
    float* out = (float*)d_out;

    enc_kernel<<<32, 32>>>(X, w1, b1, w2, b2, lng, lnb, w3, b3);
    incr_kernel<<<32, 128>>>(cw1, cb1, cw2, cb2);
    zeta_kernel<<<1, 1024>>>(out);
    sym_kernel<<<528, 256>>>(X);
    topk_kernel<<<1024, 1024>>>(y, out);
}